// round 11
// baseline (speedup 1.0000x reference)
#include <cuda_runtime.h>
#include <cuda_bf16.h>
#include <cstdint>

#define NE 50000
#define EDGES 500000
#define NREL 200
#define RANK 128
#define SLOPE 0.22916666666666666f   // (1/8 + 1/3)/2

// ---------------- scratch (device globals; no allocation allowed) ----------------
__device__ float g_h2[NE * RANK];        // hidden state after layer 0
__device__ float g_acc[NE * RANK];       // aggregation result (norm-folded)
__device__ int   g_deg[NE];              // in-degree
__device__ int   g_off[NE + 1];          // CSR offsets
__device__ int   g_cur[NE];              // CSR fill cursors
__device__ int2  g_edges[EDGES];         // CSR-permuted (src, etype)
__device__ int   g_zlist[NE];            // rows with in-degree == 0
__device__ int   g_zcount;
__device__ unsigned short g_whi[4 * RANK * RANK];  // bf16 hi of [WnL0, WlL0, WnL1, WlL1]
__device__ unsigned short g_wlo[4 * RANK * RANK];  // bf16 lo

// ======================= CSR build kernels =======================

__global__ void hist_kernel(const int* __restrict__ dst, int* __restrict__ deg) {
    int i = blockIdx.x * blockDim.x + threadIdx.x;
    if (i < EDGES) atomicAdd(&deg[dst[i]], 1);
}

// single-block exclusive scan of deg -> off (and cur); 1024 threads
__global__ void scan_kernel(const int* __restrict__ deg,
                            int* __restrict__ off, int* __restrict__ cur) {
    __shared__ int part[1024];
    const int CH = (NE + 1023) / 1024;   // 49
    int tid  = threadIdx.x;
    int base = tid * CH;
    int s = 0;
#pragma unroll 1
    for (int i = 0; i < CH; i++) {
        int idx = base + i;
        if (idx < NE) s += deg[idx];
    }
    part[tid] = s;
    __syncthreads();
    for (int d = 1; d < 1024; d <<= 1) {
        int t = (tid >= d) ? part[tid - d] : 0;
        __syncthreads();
        part[tid] += t;
        __syncthreads();
    }
    int run = part[tid] - s;
#pragma unroll 1
    for (int i = 0; i < CH; i++) {
        int idx = base + i;
        if (idx < NE) {
            off[idx] = run;
            cur[idx] = run;
            run += deg[idx];
        }
    }
    if (tid == 1023) off[NE] = EDGES;
}

__global__ void permute_kernel(const int* __restrict__ src,
                               const int* __restrict__ dst,
                               const int* __restrict__ et,
                               int* __restrict__ cur, int2* __restrict__ edges) {
    int i = blockIdx.x * blockDim.x + threadIdx.x;
    if (i < EDGES) {
        int p = atomicAdd(&cur[dst[i]], 1);
        edges[p] = make_int2(src[i], et[i]);
    }
}

__global__ void build_zlist_kernel(const int* __restrict__ deg,
                                   int* __restrict__ zlist, int* __restrict__ zcount) {
    int i = blockIdx.x * blockDim.x + threadIdx.x;
    if (i < NE && deg[i] == 0) {
        int p = atomicAdd(zcount, 1);
        zlist[p] = i;
    }
}

// W pre-split: fp32 -> bf16 hi/lo. layout: mat 0 = WnL0, 1 = WlL0, 2 = WnL1, 3 = WlL1
__global__ void wsplit_kernel(const float* __restrict__ Wn, const float* __restrict__ Wl,
                              unsigned short* __restrict__ whi, unsigned short* __restrict__ wlo) {
    int i = blockIdx.x * blockDim.x + threadIdx.x;
    if (i >= 4 * RANK * RANK) return;
    int mat = i >> 14, idx = i & 16383;
    const float* p = (mat == 0) ? Wn : (mat == 1) ? Wl
                    : (mat == 2) ? (Wn + RANK * RANK) : (Wl + RANK * RANK);
    float v = p[idx];
    __nv_bfloat16 h = __float2bfloat16(v);
    float l = v - __bfloat162float(h);
    whi[i] = __bfloat16_as_ushort(h);
    wlo[i] = __bfloat16_as_ushort(__float2bfloat16(l));
}

// ======================= gather aggregation (atomic-free, MLP-deep) =======================
// acc[n] = norm[n] * sum over incoming edges of (h[src] + rel[etype]).
// One warp per node. Full 8-edge blocks: lanes 0-7 load the edge block in one
// coalesced access, indices broadcast by shfl, then all 16 LDG.128 issue
// back-to-back (MLP ~16). Remainder (<8 edges) handled serially.
__global__ void gather_kernel(const float* __restrict__ h,
                              const float* __restrict__ rel,
                              const int2* __restrict__ edges,
                              const int* __restrict__ off,
                              const float* __restrict__ norm,
                              float* __restrict__ acc) {
    int lane = threadIdx.x & 31;
    int warp = (blockIdx.x * blockDim.x + threadIdx.x) >> 5;
    if (warp >= NE) return;
    int n   = warp;
    int col = lane * 4;
    int e0 = off[n], e1 = off[n + 1];
    float a0 = 0.f, a1 = 0.f, a2 = 0.f, a3 = 0.f;

    int base = e0;
#pragma unroll 1
    for (; base + 8 <= e1; base += 8) {
        int2 eb = edges[base + (lane & 7)];
        float4 hv[8], rv[8];
#pragma unroll
        for (int j = 0; j < 8; j++) {
            int sj = __shfl_sync(0xffffffffu, eb.x, j);
            int tj = __shfl_sync(0xffffffffu, eb.y, j);
            hv[j] = *(const float4*)(h   + (size_t)sj * RANK + col);
            rv[j] = *(const float4*)(rel + (size_t)tj * RANK + col);
        }
#pragma unroll
        for (int j = 0; j < 8; j++) {
            a0 += hv[j].x + rv[j].x; a1 += hv[j].y + rv[j].y;
            a2 += hv[j].z + rv[j].z; a3 += hv[j].w + rv[j].w;
        }
    }
    // remainder (< 8 edges)
#pragma unroll 1
    for (; base < e1; base++) {
        int2 se = edges[base];
        float4 hv = *(const float4*)(h   + (size_t)se.x * RANK + col);
        float4 rv = *(const float4*)(rel + (size_t)se.y * RANK + col);
        a0 += hv.x + rv.x; a1 += hv.y + rv.y;
        a2 += hv.z + rv.z; a3 += hv.w + rv.w;
    }
    float nv = norm[n];
    *(float4*)(acc + (size_t)n * RANK + col) =
        make_float4(a0 * nv, a1 * nv, a2 * nv, a3 * nv);
}

// Rows with in_deg==0 (expected ~2): out[row] = leaky(h[row] @ Wa)
__global__ void fixup_kernel(const float* __restrict__ B,
                             const float* __restrict__ Wa,
                             const int* __restrict__ zlist,
                             const int* __restrict__ zcount,
                             float* __restrict__ out) {
    int lane  = threadIdx.x & 31;
    int warp  = (blockIdx.x * blockDim.x + threadIdx.x) >> 5;
    int nwarp = (gridDim.x * blockDim.x) >> 5;
    int cnt   = *zcount;
    for (int idx = warp; idx < cnt; idx += nwarp) {
        int row = zlist[idx];
        float a0 = 0.f, a1 = 0.f, a2 = 0.f, a3 = 0.f;
        const float* brow = B + (size_t)row * RANK;
#pragma unroll 4
        for (int k = 0; k < RANK; k++) {
            float hk = __ldg(brow + k);
            float4 w = *(const float4*)(Wa + (size_t)k * RANK + lane * 4);
            a0 = fmaf(hk, w.x, a0); a1 = fmaf(hk, w.y, a1);
            a2 = fmaf(hk, w.z, a2); a3 = fmaf(hk, w.w, a3);
        }
        float4 v;
        v.x = (a0 >= 0.f) ? a0 : a0 * SLOPE;
        v.y = (a1 >= 0.f) ? a1 : a1 * SLOPE;
        v.z = (a2 >= 0.f) ? a2 : a2 * SLOPE;
        v.w = (a3 >= 0.f) ? a3 : a3 * SLOPE;
        *(float4*)(out + (size_t)row * RANK + lane * 4) = v;
    }
}

// ======================= HMMA (mma.sync) GEMM kernel =======================
// out = leaky( acc @ Wn + h @ Wl )   (norm already folded into acc).
// 64x128 tile per CTA, bf16 hi/lo split (3 MMA terms). W pre-split. 2 CTAs/SM.

__device__ __forceinline__ uint32_t smem_u32(const void* p) {
    uint32_t a;
    asm("{ .reg .u64 t; cvta.to.shared.u64 t, %1; cvt.u32.u64 %0, t; }" : "=r"(a) : "l"(p));
    return a;
}
__device__ __forceinline__ void ldsm_x4(uint32_t& r0, uint32_t& r1, uint32_t& r2, uint32_t& r3,
                                        uint32_t addr) {
    asm volatile("ldmatrix.sync.aligned.m8n8.x4.shared.b16 {%0,%1,%2,%3}, [%4];"
                 : "=r"(r0), "=r"(r1), "=r"(r2), "=r"(r3) : "r"(addr));
}
__device__ __forceinline__ void ldsm_x4_t(uint32_t& r0, uint32_t& r1, uint32_t& r2, uint32_t& r3,
                                          uint32_t addr) {
    asm volatile("ldmatrix.sync.aligned.m8n8.x4.trans.shared.b16 {%0,%1,%2,%3}, [%4];"
                 : "=r"(r0), "=r"(r1), "=r"(r2), "=r"(r3) : "r"(addr));
}
__device__ __forceinline__ void mma16816(float* c, const uint32_t* a, const uint32_t* b) {
    asm volatile(
        "mma.sync.aligned.m16n8k16.row.col.f32.bf16.bf16.f32 "
        "{%0,%1,%2,%3}, {%4,%5,%6,%7}, {%8,%9}, {%0,%1,%2,%3};"
        : "+f"(c[0]), "+f"(c[1]), "+f"(c[2]), "+f"(c[3])
        : "r"(a[0]), "r"(a[1]), "r"(a[2]), "r"(a[3]), "r"(b[0]), "r"(b[1]));
}

#define TSTRIDE 136                     // bf16 elements per smem row (128 + 8 pad)
#define XTILE_B (64 * TSTRIDE * 2)      // 17408 bytes (64-row X tile)
#define WTILE_B (128 * TSTRIDE * 2)     // 34816 bytes (128-row W tile)
#define XHI 0
#define XLO (XTILE_B)
#define WHI (2 * XTILE_B)
#define WLO (2 * XTILE_B + WTILE_B)
#define SM_TOTAL (2 * XTILE_B + 2 * WTILE_B)   // 104448 bytes -> 2 CTAs/SM

// split 8 fp32 -> bf16 hi / bf16 lo, store 16B each into two tiles
__device__ __forceinline__ void split_store8(char* sm, uint32_t hi_base, uint32_t lo_base,
                                             uint32_t byteoff, const float* v) {
    uint32_t hp[4], lp[4];
#pragma unroll
    for (int j = 0; j < 4; j++) {
        __nv_bfloat16 h0 = __float2bfloat16(v[2 * j]);
        __nv_bfloat16 h1 = __float2bfloat16(v[2 * j + 1]);
        float l0 = v[2 * j]     - __bfloat162float(h0);
        float l1 = v[2 * j + 1] - __bfloat162float(h1);
        __nv_bfloat16 g0 = __float2bfloat16(l0);
        __nv_bfloat16 g1 = __float2bfloat16(l1);
        hp[j] = (uint32_t)__bfloat16_as_ushort(h0) | ((uint32_t)__bfloat16_as_ushort(h1) << 16);
        lp[j] = (uint32_t)__bfloat16_as_ushort(g0) | ((uint32_t)__bfloat16_as_ushort(g1) << 16);
    }
    *(uint4*)(sm + hi_base + byteoff) = make_uint4(hp[0], hp[1], hp[2], hp[3]);
    *(uint4*)(sm + lo_base + byteoff) = make_uint4(lp[0], lp[1], lp[2], lp[3]);
}

__global__ __launch_bounds__(256, 2)
void gemm_mma_kernel(const float* __restrict__ A,     // acc (norm-folded) [NE,128]
                     const float* __restrict__ B,     // h   [NE,128]
                     const unsigned short* __restrict__ whi,  // layer base: [Wn_hi | Wl_hi]
                     const unsigned short* __restrict__ wlo,
                     float* __restrict__ out) {
    extern __shared__ char sm[];
    uint32_t smb = smem_u32(sm);
    int tid    = threadIdx.x;
    int lane   = tid & 31;
    int wid    = tid >> 5;
    int warp_m = wid & 1;     // 32-row band within the 64-row tile
    int warp_n = wid >> 1;    // 32-col band (4 warps cover N=128)
    int row0   = blockIdx.x * 64;

    float c[2][4][4];
#pragma unroll
    for (int mf = 0; mf < 2; mf++)
#pragma unroll
        for (int nf = 0; nf < 4; nf++)
#pragma unroll
            for (int q = 0; q < 4; q++) c[mf][nf][q] = 0.f;

#pragma unroll 1
    for (int half = 0; half < 2; half++) {
        const float* X = (half == 0) ? A : B;
        const unsigned short* WH = whi + half * (RANK * RANK);
        const unsigned short* WL = wlo + half * (RANK * RANK);

        // X tile -> Xhi/Xlo  [row][k], row-major, stride 136 (64 rows x 16 kchunks)
#pragma unroll 1
        for (int i = tid; i < 1024; i += 256) {
            int row = i >> 4;
            int k0  = (i & 15) << 3;
            int grow = row0 + row;
            float v[8];
            if (grow < NE) {
                float4 x0 = *(const float4*)(X + (size_t)grow * RANK + k0);
                float4 x1 = *(const float4*)(X + (size_t)grow * RANK + k0 + 4);
                v[0] = x0.x; v[1] = x0.y; v[2] = x0.z; v[3] = x0.w;
                v[4] = x1.x; v[5] = x1.y; v[6] = x1.z; v[7] = x1.w;
            } else {
#pragma unroll
                for (int j = 0; j < 8; j++) v[j] = 0.f;
            }
            split_store8(sm, XHI, XLO, (uint32_t)(row * TSTRIDE + k0) * 2, v);
        }

        // W tile: plain bf16 copies from pre-split global [k][n] into padded smem
#pragma unroll 1
        for (int i = tid; i < 2048; i += 256) {
            int k  = i >> 4;
            int n0 = (i & 15) << 3;
            uint4 hv = *(const uint4*)(WH + k * RANK + n0);
            uint4 lv = *(const uint4*)(WL + k * RANK + n0);
            uint32_t off = (uint32_t)(k * TSTRIDE + n0) * 2;
            *(uint4*)(sm + WHI + off) = hv;
            *(uint4*)(sm + WLO + off) = lv;
        }
        __syncthreads();

#pragma unroll 1
        for (int ks = 0; ks < 8; ks++) {
            int k0 = ks * 16;
            // A fragments (hi, lo) for 2 m16 blocks
            uint32_t aH[2][4], aL[2][4];
#pragma unroll
            for (int mf = 0; mf < 2; mf++) {
                int row = warp_m * 32 + mf * 16 + (lane & 15);
                int col = k0 + (lane >> 4) * 8;
                uint32_t off = (uint32_t)(row * TSTRIDE + col) * 2;
                ldsm_x4(aH[mf][0], aH[mf][1], aH[mf][2], aH[mf][3], smb + XHI + off);
                ldsm_x4(aL[mf][0], aL[mf][1], aL[mf][2], aL[mf][3], smb + XLO + off);
            }
            // B fragments (hi, lo) for 4 n8 blocks (2 ldmatrix.x4.trans of 16 cols)
            uint32_t bH[4][2], bL[4][2];
#pragma unroll
            for (int nb = 0; nb < 2; nb++) {
                int n0   = warp_n * 32 + nb * 16;
                int krow = k0 + ((lane >> 3) & 1) * 8 + (lane & 7);
                int ncol = n0 + (lane >> 4) * 8;
                uint32_t off = (uint32_t)(krow * TSTRIDE + ncol) * 2;
                uint32_t r0, r1, r2, r3;
                ldsm_x4_t(r0, r1, r2, r3, smb + WHI + off);
                bH[nb * 2][0] = r0; bH[nb * 2][1] = r1;
                bH[nb * 2 + 1][0] = r2; bH[nb * 2 + 1][1] = r3;
                ldsm_x4_t(r0, r1, r2, r3, smb + WLO + off);
                bL[nb * 2][0] = r0; bL[nb * 2][1] = r1;
                bL[nb * 2 + 1][0] = r2; bL[nb * 2 + 1][1] = r3;
            }
#pragma unroll
            for (int mf = 0; mf < 2; mf++)
#pragma unroll
                for (int nf = 0; nf < 4; nf++) {
                    mma16816(c[mf][nf], aH[mf], bH[nf]);   // hi*hi
                    mma16816(c[mf][nf], aH[mf], bL[nf]);   // hi*lo
                    mma16816(c[mf][nf], aL[mf], bH[nf]);   // lo*hi
                }
        }
        __syncthreads();
    }

    // ---------- epilogue: leaky relu + store ----------
    int r_in  = lane >> 2;
    int c_in  = (lane & 3) * 2;
#pragma unroll
    for (int mf = 0; mf < 2; mf++) {
        int rbase = row0 + warp_m * 32 + mf * 16 + r_in;
#pragma unroll
        for (int nf = 0; nf < 4; nf++) {
            int col = warp_n * 32 + nf * 8 + c_in;
            float x0 = c[mf][nf][0], x1 = c[mf][nf][1];
            float x2 = c[mf][nf][2], x3 = c[mf][nf][3];
            x0 = (x0 >= 0.f) ? x0 : x0 * SLOPE;
            x1 = (x1 >= 0.f) ? x1 : x1 * SLOPE;
            x2 = (x2 >= 0.f) ? x2 : x2 * SLOPE;
            x3 = (x3 >= 0.f) ? x3 : x3 * SLOPE;
            if (rbase < NE)
                *(float2*)(out + (size_t)rbase * RANK + col) = make_float2(x0, x1);
            if (rbase + 8 < NE)
                *(float2*)(out + (size_t)(rbase + 8) * RANK + col) = make_float2(x2, x3);
        }
    }
}

// ======================= launch =======================
extern "C" void kernel_launch(void* const* d_in, const int* in_sizes, int n_in,
                              void* d_out, int out_size) {
    const float* ent  = (const float*)d_in[0];
    const float* rel  = (const float*)d_in[1];
    const float* norm = (const float*)d_in[2];
    const float* Wn   = (const float*)d_in[3];
    const float* Wl   = (const float*)d_in[4];
    const float* Wa   = (const float*)d_in[5];
    const int*   src  = (const int*)d_in[6];
    const int*   dst  = (const int*)d_in[7];
    const int*   et   = (const int*)d_in[8];
    float* out = (float*)d_out;

    void *p_h2, *p_acc, *p_deg, *p_off, *p_cur, *p_edges, *p_zlist, *p_zcount, *p_whi, *p_wlo;
    cudaGetSymbolAddress(&p_h2, g_h2);
    cudaGetSymbolAddress(&p_acc, g_acc);
    cudaGetSymbolAddress(&p_deg, g_deg);
    cudaGetSymbolAddress(&p_off, g_off);
    cudaGetSymbolAddress(&p_cur, g_cur);
    cudaGetSymbolAddress(&p_edges, g_edges);
    cudaGetSymbolAddress(&p_zlist, g_zlist);
    cudaGetSymbolAddress(&p_zcount, g_zcount);
    cudaGetSymbolAddress(&p_whi, g_whi);
    cudaGetSymbolAddress(&p_wlo, g_wlo);
    float* h2    = (float*)p_h2;
    float* acc   = (float*)p_acc;
    int*   deg   = (int*)p_deg;
    int*   off   = (int*)p_off;
    int*   cur   = (int*)p_cur;
    int2*  edges = (int2*)p_edges;
    int*   zlist = (int*)p_zlist;
    int*   zcount = (int*)p_zcount;
    unsigned short* whi = (unsigned short*)p_whi;
    unsigned short* wlo = (unsigned short*)p_wlo;

    const int WOFF = RANK * RANK;  // per-layer weight offset

    cudaFuncSetAttribute(gemm_mma_kernel, cudaFuncAttributeMaxDynamicSharedMemorySize, SM_TOTAL);

    // ---- CSR build + W pre-split (once per call; reused across layers) ----
    cudaMemsetAsync(deg, 0, NE * sizeof(int), 0);
    cudaMemsetAsync(zcount, 0, sizeof(int), 0);
    hist_kernel<<<(EDGES + 255) / 256, 256>>>(dst, deg);
    scan_kernel<<<1, 1024>>>(deg, off, cur);
    build_zlist_kernel<<<(NE + 255) / 256, 256>>>(deg, zlist, zcount);
    permute_kernel<<<(EDGES + 255) / 256, 256>>>(src, dst, et, cur, edges);
    wsplit_kernel<<<(4 * RANK * RANK + 255) / 256, 256>>>(Wn, Wl, whi, wlo);

    const int tiles = (NE + 63) / 64;
    const int gather_blocks = (NE * 32 + 255) / 256;   // one warp per node, exactly

    // ---- layer 0: h = ent_emb ----
    gather_kernel<<<gather_blocks, 256>>>(ent, rel, edges, off, norm, acc);
    gemm_mma_kernel<<<tiles, 256, SM_TOTAL>>>(acc, ent, whi, wlo, h2);
    fixup_kernel<<<32, 256>>>(ent, Wa, zlist, zcount, h2);

    // ---- layer 1: h = h2, write final output ----
    gather_kernel<<<gather_blocks, 256>>>(h2, rel, edges, off, norm, acc);
    gemm_mma_kernel<<<tiles, 256, SM_TOTAL>>>(acc, h2, whi + 2 * WOFF, wlo + 2 * WOFF, out);
    fixup_kernel<<<32, 256>>>(h2, Wa + WOFF, zlist, zcount, out);
}

// round 12
// speedup vs baseline: 1.1738x; 1.1738x over previous
#include <cuda_runtime.h>
#include <cuda_bf16.h>
#include <cstdint>

#define NE 50000
#define EDGES 500000
#define NREL 200
#define RANK 128
#define SLOPE 0.22916666666666666f   // (1/8 + 1/3)/2

// ---------------- scratch (device globals; no allocation allowed) ----------------
__device__ float g_h2[NE * RANK];    // hidden state after layer 0
__device__ float g_acc[NE * RANK];   // scatter accumulator
__device__ int   g_hasin[NE];        // in-degree > 0 mask
__device__ int   g_zlist[NE];        // rows with in-degree == 0
__device__ int   g_zcount;
__device__ unsigned short g_whi[4 * RANK * RANK];  // bf16 hi of [WnL0, WlL0, WnL1, WlL1]
__device__ unsigned short g_wlo[4 * RANK * RANK];  // bf16 lo

// ======================= small helper kernels =======================

__global__ void mark_hasin_kernel(const int* __restrict__ dst, int* __restrict__ hasin) {
    int i = blockIdx.x * blockDim.x + threadIdx.x;
    if (i < EDGES) hasin[dst[i]] = 1;
}

__global__ void build_zlist_kernel(const int* __restrict__ hasin,
                                   int* __restrict__ zlist, int* __restrict__ zcount) {
    int i = blockIdx.x * blockDim.x + threadIdx.x;
    if (i < NE && !hasin[i]) {
        int p = atomicAdd(zcount, 1);
        zlist[p] = i;
    }
}

// W pre-split: fp32 -> bf16 hi/lo. layout: mat 0 = WnL0, 1 = WlL0, 2 = WnL1, 3 = WlL1
__global__ void wsplit_kernel(const float* __restrict__ Wn, const float* __restrict__ Wl,
                              unsigned short* __restrict__ whi, unsigned short* __restrict__ wlo) {
    int i = blockIdx.x * blockDim.x + threadIdx.x;
    if (i >= 4 * RANK * RANK) return;
    int mat = i >> 14, idx = i & 16383;
    const float* p = (mat == 0) ? Wn : (mat == 1) ? Wl
                    : (mat == 2) ? (Wn + RANK * RANK) : (Wl + RANK * RANK);
    float v = p[idx];
    __nv_bfloat16 h = __float2bfloat16(v);
    float l = v - __bfloat162float(h);
    whi[i] = __bfloat16_as_ushort(h);
    wlo[i] = __bfloat16_as_ushort(__float2bfloat16(l));
}

// acc[dst] += h[src] + rel[etype]  (one warp per edge; manual 2-edge unroll so
// all four gather LDG.128 are in flight before the two red.v4 issue)
__global__ void scatter_kernel(const float* __restrict__ h,
                               const float* __restrict__ rel,
                               const int* __restrict__ src,
                               const int* __restrict__ dst,
                               const int* __restrict__ et,
                               float* __restrict__ acc) {
    int lane  = threadIdx.x & 31;
    int warp  = (blockIdx.x * blockDim.x + threadIdx.x) >> 5;
    int nwarp = (gridDim.x * blockDim.x) >> 5;
    int col   = lane * 4;
    // EDGES is even; process disjoint pairs
    for (int e = warp * 2; e + 1 < EDGES; e += 2 * nwarp) {
        int s0 = src[e],     d0 = dst[e],     t0 = et[e];
        int s1 = src[e + 1], d1 = dst[e + 1], t1 = et[e + 1];
        float4 hv0 = *(const float4*)(h   + (size_t)s0 * RANK + col);
        float4 hv1 = *(const float4*)(h   + (size_t)s1 * RANK + col);
        float4 rv0 = *(const float4*)(rel + (size_t)t0 * RANK + col);
        float4 rv1 = *(const float4*)(rel + (size_t)t1 * RANK + col);
        float4 v0, v1;
        v0.x = hv0.x + rv0.x; v0.y = hv0.y + rv0.y; v0.z = hv0.z + rv0.z; v0.w = hv0.w + rv0.w;
        v1.x = hv1.x + rv1.x; v1.y = hv1.y + rv1.y; v1.z = hv1.z + rv1.z; v1.w = hv1.w + rv1.w;
        float* p0 = acc + (size_t)d0 * RANK + col;
        float* p1 = acc + (size_t)d1 * RANK + col;
        asm volatile("red.global.add.v4.f32 [%0], {%1, %2, %3, %4};"
                     :: "l"(p0), "f"(v0.x), "f"(v0.y), "f"(v0.z), "f"(v0.w) : "memory");
        asm volatile("red.global.add.v4.f32 [%0], {%1, %2, %3, %4};"
                     :: "l"(p1), "f"(v1.x), "f"(v1.y), "f"(v1.z), "f"(v1.w) : "memory");
    }
}

// Rows with in_deg==0 (expected ~2): out[row] = leaky(h[row] @ Wa)
__global__ void fixup_kernel(const float* __restrict__ B,
                             const float* __restrict__ Wa,
                             const int* __restrict__ zlist,
                             const int* __restrict__ zcount,
                             float* __restrict__ out) {
    int lane  = threadIdx.x & 31;
    int warp  = (blockIdx.x * blockDim.x + threadIdx.x) >> 5;
    int nwarp = (gridDim.x * blockDim.x) >> 5;
    int cnt   = *zcount;
    for (int idx = warp; idx < cnt; idx += nwarp) {
        int row = zlist[idx];
        float a0 = 0.f, a1 = 0.f, a2 = 0.f, a3 = 0.f;
        const float* brow = B + (size_t)row * RANK;
#pragma unroll 4
        for (int k = 0; k < RANK; k++) {
            float hk = __ldg(brow + k);
            float4 w = *(const float4*)(Wa + (size_t)k * RANK + lane * 4);
            a0 = fmaf(hk, w.x, a0); a1 = fmaf(hk, w.y, a1);
            a2 = fmaf(hk, w.z, a2); a3 = fmaf(hk, w.w, a3);
        }
        float4 v;
        v.x = (a0 >= 0.f) ? a0 : a0 * SLOPE;
        v.y = (a1 >= 0.f) ? a1 : a1 * SLOPE;
        v.z = (a2 >= 0.f) ? a2 : a2 * SLOPE;
        v.w = (a3 >= 0.f) ? a3 : a3 * SLOPE;
        *(float4*)(out + (size_t)row * RANK + lane * 4) = v;
    }
}

// ======================= HMMA (mma.sync) GEMM kernel =======================
// out = leaky( (norm*acc) @ Wn + h @ Wl ), 64x64 output tile per CTA (N split
// in 2), bf16 hi/lo split (3 MMA terms). W pre-split in global. 3 CTAs/SM.

__device__ __forceinline__ uint32_t smem_u32(const void* p) {
    uint32_t a;
    asm("{ .reg .u64 t; cvta.to.shared.u64 t, %1; cvt.u32.u64 %0, t; }" : "=r"(a) : "l"(p));
    return a;
}
__device__ __forceinline__ void ldsm_x4(uint32_t& r0, uint32_t& r1, uint32_t& r2, uint32_t& r3,
                                        uint32_t addr) {
    asm volatile("ldmatrix.sync.aligned.m8n8.x4.shared.b16 {%0,%1,%2,%3}, [%4];"
                 : "=r"(r0), "=r"(r1), "=r"(r2), "=r"(r3) : "r"(addr));
}
__device__ __forceinline__ void ldsm_x4_t(uint32_t& r0, uint32_t& r1, uint32_t& r2, uint32_t& r3,
                                          uint32_t addr) {
    asm volatile("ldmatrix.sync.aligned.m8n8.x4.trans.shared.b16 {%0,%1,%2,%3}, [%4];"
                 : "=r"(r0), "=r"(r1), "=r"(r2), "=r"(r3) : "r"(addr));
}
__device__ __forceinline__ void mma16816(float* c, const uint32_t* a, const uint32_t* b) {
    asm volatile(
        "mma.sync.aligned.m16n8k16.row.col.f32.bf16.bf16.f32 "
        "{%0,%1,%2,%3}, {%4,%5,%6,%7}, {%8,%9}, {%0,%1,%2,%3};"
        : "+f"(c[0]), "+f"(c[1]), "+f"(c[2]), "+f"(c[3])
        : "r"(a[0]), "r"(a[1]), "r"(a[2]), "r"(a[3]), "r"(b[0]), "r"(b[1]));
}

#define TSTRIDE 136                     // X smem row: 128 + 8 pad bf16
#define WSTRIDE 72                      // W smem row: 64 + 8 pad bf16
#define XTILE_B (64 * TSTRIDE * 2)      // 17408 bytes (64-row X tile)
#define WTILE_B (128 * WSTRIDE * 2)     // 18432 bytes (128k x 64n W tile)
#define XHI 0
#define XLO (XTILE_B)
#define WHI (2 * XTILE_B)
#define WLO (2 * XTILE_B + WTILE_B)
#define SM_TOTAL (2 * XTILE_B + 2 * WTILE_B)   // 71680 bytes -> 3 CTAs/SM

// split 8 fp32 -> bf16 hi / bf16 lo, store 16B each into two tiles
__device__ __forceinline__ void split_store8(char* sm, uint32_t hi_base, uint32_t lo_base,
                                             uint32_t byteoff, const float* v) {
    uint32_t hp[4], lp[4];
#pragma unroll
    for (int j = 0; j < 4; j++) {
        __nv_bfloat16 h0 = __float2bfloat16(v[2 * j]);
        __nv_bfloat16 h1 = __float2bfloat16(v[2 * j + 1]);
        float l0 = v[2 * j]     - __bfloat162float(h0);
        float l1 = v[2 * j + 1] - __bfloat162float(h1);
        __nv_bfloat16 g0 = __float2bfloat16(l0);
        __nv_bfloat16 g1 = __float2bfloat16(l1);
        hp[j] = (uint32_t)__bfloat16_as_ushort(h0) | ((uint32_t)__bfloat16_as_ushort(h1) << 16);
        lp[j] = (uint32_t)__bfloat16_as_ushort(g0) | ((uint32_t)__bfloat16_as_ushort(g1) << 16);
    }
    *(uint4*)(sm + hi_base + byteoff) = make_uint4(hp[0], hp[1], hp[2], hp[3]);
    *(uint4*)(sm + lo_base + byteoff) = make_uint4(lp[0], lp[1], lp[2], lp[3]);
}

__global__ __launch_bounds__(256, 3)
void gemm_mma_kernel(const float* __restrict__ A,     // acc [NE,128]
                     const float* __restrict__ B,     // h   [NE,128]
                     const unsigned short* __restrict__ whi,  // layer base: [Wn_hi | Wl_hi]
                     const unsigned short* __restrict__ wlo,
                     const float* __restrict__ norm,
                     float* __restrict__ out) {
    extern __shared__ char sm[];
    uint32_t smb = smem_u32(sm);
    int tid    = threadIdx.x;
    int lane   = tid & 31;
    int wid    = tid >> 5;
    int warp_m = wid & 1;     // 32-row band within the 64-row tile
    int warp_n = wid >> 1;    // 16-col band (4 warps cover N=64)
    int ncol0  = (blockIdx.x & 1) * 64;    // which 64-col half of W / out
    int row0   = (blockIdx.x >> 1) * 64;

    float c[2][2][4];
#pragma unroll
    for (int mf = 0; mf < 2; mf++)
#pragma unroll
        for (int nf = 0; nf < 2; nf++)
#pragma unroll
            for (int q = 0; q < 4; q++) c[mf][nf][q] = 0.f;

#pragma unroll 1
    for (int half = 0; half < 2; half++) {
        const float* X = (half == 0) ? A : B;
        const unsigned short* WH = whi + half * (RANK * RANK);
        const unsigned short* WL = wlo + half * (RANK * RANK);

        // X tile -> Xhi/Xlo  [row][k], row-major, stride 136 (64 rows x 16 kchunks)
#pragma unroll 1
        for (int i = tid; i < 1024; i += 256) {
            int row = i >> 4;
            int k0  = (i & 15) << 3;
            int grow = row0 + row;
            float v[8];
            if (grow < NE) {
                float4 x0 = *(const float4*)(X + (size_t)grow * RANK + k0);
                float4 x1 = *(const float4*)(X + (size_t)grow * RANK + k0 + 4);
                float s = (half == 0) ? __ldg(norm + grow) : 1.0f;
                v[0] = x0.x * s; v[1] = x0.y * s; v[2] = x0.z * s; v[3] = x0.w * s;
                v[4] = x1.x * s; v[5] = x1.y * s; v[6] = x1.z * s; v[7] = x1.w * s;
            } else {
#pragma unroll
                for (int j = 0; j < 8; j++) v[j] = 0.f;
            }
            split_store8(sm, XHI, XLO, (uint32_t)(row * TSTRIDE + k0) * 2, v);
        }

        // W tile: bf16 copies of cols [ncol0, ncol0+64), all 128 k-rows
#pragma unroll 1
        for (int i = tid; i < 1024; i += 256) {
            int k  = i >> 3;
            int n0 = (i & 7) << 3;
            uint4 hv = *(const uint4*)(WH + k * RANK + ncol0 + n0);
            uint4 lv = *(const uint4*)(WL + k * RANK + ncol0 + n0);
            uint32_t off = (uint32_t)(k * WSTRIDE + n0) * 2;
            *(uint4*)(sm + WHI + off) = hv;
            *(uint4*)(sm + WLO + off) = lv;
        }
        __syncthreads();

#pragma unroll 1
        for (int ks = 0; ks < 8; ks++) {
            int k0 = ks * 16;
            // A fragments (hi, lo) for 2 m16 blocks
            uint32_t aH[2][4], aL[2][4];
#pragma unroll
            for (int mf = 0; mf < 2; mf++) {
                int row = warp_m * 32 + mf * 16 + (lane & 15);
                int col = k0 + (lane >> 4) * 8;
                uint32_t off = (uint32_t)(row * TSTRIDE + col) * 2;
                ldsm_x4(aH[mf][0], aH[mf][1], aH[mf][2], aH[mf][3], smb + XHI + off);
                ldsm_x4(aL[mf][0], aL[mf][1], aL[mf][2], aL[mf][3], smb + XLO + off);
            }
            // B fragments (hi, lo): one ldmatrix.x4.trans covers this warp's 16 cols
            uint32_t bH[2][2], bL[2][2];
            {
                int n0   = warp_n * 16;
                int krow = k0 + ((lane >> 3) & 1) * 8 + (lane & 7);
                int ncol = n0 + (lane >> 4) * 8;
                uint32_t off = (uint32_t)(krow * WSTRIDE + ncol) * 2;
                uint32_t r0, r1, r2, r3;
                ldsm_x4_t(r0, r1, r2, r3, smb + WHI + off);
                bH[0][0] = r0; bH[0][1] = r1; bH[1][0] = r2; bH[1][1] = r3;
                ldsm_x4_t(r0, r1, r2, r3, smb + WLO + off);
                bL[0][0] = r0; bL[0][1] = r1; bL[1][0] = r2; bL[1][1] = r3;
            }
#pragma unroll
            for (int mf = 0; mf < 2; mf++)
#pragma unroll
                for (int nf = 0; nf < 2; nf++) {
                    mma16816(c[mf][nf], aH[mf], bH[nf]);   // hi*hi
                    mma16816(c[mf][nf], aH[mf], bL[nf]);   // hi*lo
                    mma16816(c[mf][nf], aL[mf], bH[nf]);   // lo*hi
                }
        }
        __syncthreads();
    }

    // ---------- epilogue: leaky relu + store ----------
    int r_in  = lane >> 2;
    int c_in  = (lane & 3) * 2;
#pragma unroll
    for (int mf = 0; mf < 2; mf++) {
        int rbase = row0 + warp_m * 32 + mf * 16 + r_in;
#pragma unroll
        for (int nf = 0; nf < 2; nf++) {
            int col = ncol0 + warp_n * 16 + nf * 8 + c_in;
            float x0 = c[mf][nf][0], x1 = c[mf][nf][1];
            float x2 = c[mf][nf][2], x3 = c[mf][nf][3];
            x0 = (x0 >= 0.f) ? x0 : x0 * SLOPE;
            x1 = (x1 >= 0.f) ? x1 : x1 * SLOPE;
            x2 = (x2 >= 0.f) ? x2 : x2 * SLOPE;
            x3 = (x3 >= 0.f) ? x3 : x3 * SLOPE;
            if (rbase < NE)
                *(float2*)(out + (size_t)rbase * RANK + col) = make_float2(x0, x1);
            if (rbase + 8 < NE)
                *(float2*)(out + (size_t)(rbase + 8) * RANK + col) = make_float2(x2, x3);
        }
    }
}

// ======================= launch =======================
extern "C" void kernel_launch(void* const* d_in, const int* in_sizes, int n_in,
                              void* d_out, int out_size) {
    const float* ent  = (const float*)d_in[0];
    const float* rel  = (const float*)d_in[1];
    const float* norm = (const float*)d_in[2];
    const float* Wn   = (const float*)d_in[3];
    const float* Wl   = (const float*)d_in[4];
    const float* Wa   = (const float*)d_in[5];
    const int*   src  = (const int*)d_in[6];
    const int*   dst  = (const int*)d_in[7];
    const int*   et   = (const int*)d_in[8];
    float* out = (float*)d_out;

    void *p_h2, *p_acc, *p_hasin, *p_zlist, *p_zcount, *p_whi, *p_wlo;
    cudaGetSymbolAddress(&p_h2, g_h2);
    cudaGetSymbolAddress(&p_acc, g_acc);
    cudaGetSymbolAddress(&p_hasin, g_hasin);
    cudaGetSymbolAddress(&p_zlist, g_zlist);
    cudaGetSymbolAddress(&p_zcount, g_zcount);
    cudaGetSymbolAddress(&p_whi, g_whi);
    cudaGetSymbolAddress(&p_wlo, g_wlo);
    float* h2    = (float*)p_h2;
    float* acc   = (float*)p_acc;
    int* hasin   = (int*)p_hasin;
    int* zlist   = (int*)p_zlist;
    int* zcount  = (int*)p_zcount;
    unsigned short* whi = (unsigned short*)p_whi;
    unsigned short* wlo = (unsigned short*)p_wlo;

    const int WOFF = RANK * RANK;  // per-layer weight offset

    cudaFuncSetAttribute(gemm_mma_kernel, cudaFuncAttributeMaxDynamicSharedMemorySize, SM_TOTAL);

    cudaMemsetAsync(hasin, 0, NE * sizeof(int), 0);
    cudaMemsetAsync(zcount, 0, sizeof(int), 0);
    mark_hasin_kernel<<<(EDGES + 255) / 256, 256>>>(dst, hasin);
    build_zlist_kernel<<<(NE + 255) / 256, 256>>>(hasin, zlist, zcount);
    wsplit_kernel<<<(4 * RANK * RANK + 255) / 256, 256>>>(Wn, Wl, whi, wlo);

    const int tiles = 2 * ((NE + 63) / 64);   // M-tiles x 2 N-halves

    // ---- layer 0: h = ent_emb ----
    cudaMemsetAsync(acc, 0, (size_t)NE * RANK * sizeof(float), 0);
    scatter_kernel<<<2048, 256>>>(ent, rel, src, dst, et, acc);
    gemm_mma_kernel<<<tiles, 256, SM_TOTAL>>>(acc, ent, whi, wlo, norm, h2);
    fixup_kernel<<<32, 256>>>(ent, Wa, zlist, zcount, h2);

    // ---- layer 1: h = h2, write final output ----
    cudaMemsetAsync(acc, 0, (size_t)NE * RANK * sizeof(float), 0);
    scatter_kernel<<<2048, 256>>>(h2, rel, src, dst, et, acc);
    gemm_mma_kernel<<<tiles, 256, SM_TOTAL>>>(acc, h2, whi + 2 * WOFF, wlo + 2 * WOFF, norm, out);
    fixup_kernel<<<32, 256>>>(h2, Wa + WOFF, zlist, zcount, out);
}

// round 15
// speedup vs baseline: 1.2717x; 1.0834x over previous
#include <cuda_runtime.h>
#include <cuda_bf16.h>
#include <cstdint>

#define NE 50000
#define EDGES 500000
#define NREL 200
#define RANK 128
#define SLOPE 0.22916666666666666f   // (1/8 + 1/3)/2

// ---------------- scratch (device globals; no allocation allowed) ----------------
__device__ float g_h2[NE * RANK];    // hidden state after layer 0
__device__ float g_acc[NE * RANK];   // scatter accumulator
__device__ int   g_hasin[NE];        // in-degree > 0 mask
__device__ int   g_zlist[NE];        // rows with in-degree == 0
__device__ int   g_zcount;
__device__ unsigned short g_whi[4 * RANK * RANK];  // bf16 hi of [WnL0, WlL0, WnL1, WlL1]
__device__ unsigned short g_wlo[4 * RANK * RANK];  // bf16 lo

// ======================= small helper kernels =======================

__global__ void mark_hasin_kernel(const int* __restrict__ dst, int* __restrict__ hasin) {
    int i = blockIdx.x * blockDim.x + threadIdx.x;
    if (i < EDGES) hasin[dst[i]] = 1;
}

__global__ void build_zlist_kernel(const int* __restrict__ hasin,
                                   int* __restrict__ zlist, int* __restrict__ zcount) {
    int i = blockIdx.x * blockDim.x + threadIdx.x;
    if (i < NE && !hasin[i]) {
        int p = atomicAdd(zcount, 1);
        zlist[p] = i;
    }
}

// W pre-split: fp32 -> bf16 hi/lo. layout: mat 0 = WnL0, 1 = WlL0, 2 = WnL1, 3 = WlL1
__global__ void wsplit_kernel(const float* __restrict__ Wn, const float* __restrict__ Wl,
                              unsigned short* __restrict__ whi, unsigned short* __restrict__ wlo) {
    int i = blockIdx.x * blockDim.x + threadIdx.x;
    if (i >= 4 * RANK * RANK) return;
    int mat = i >> 14, idx = i & 16383;
    const float* p = (mat == 0) ? Wn : (mat == 1) ? Wl
                    : (mat == 2) ? (Wn + RANK * RANK) : (Wl + RANK * RANK);
    float v = p[idx];
    __nv_bfloat16 h = __float2bfloat16(v);
    float l = v - __bfloat162float(h);
    whi[i] = __bfloat16_as_ushort(h);
    wlo[i] = __bfloat16_as_ushort(__float2bfloat16(l));
}

// acc[dst] += h[src] + rel[etype]  (one warp per edge; 4-edge unroll: 8 gather
// LDG.128 in flight before the 4 red.v4 issue)
__global__ void scatter_kernel(const float* __restrict__ h,
                               const float* __restrict__ rel,
                               const int* __restrict__ src,
                               const int* __restrict__ dst,
                               const int* __restrict__ et,
                               float* __restrict__ acc) {
    int lane  = threadIdx.x & 31;
    int warp  = (blockIdx.x * blockDim.x + threadIdx.x) >> 5;
    int nwarp = (gridDim.x * blockDim.x) >> 5;
    int col   = lane * 4;
    // EDGES divisible by 4; process disjoint quads
    for (int e = warp * 4; e + 3 < EDGES; e += 4 * nwarp) {
        int s[4], d[4], t[4];
#pragma unroll
        for (int j = 0; j < 4; j++) { s[j] = src[e + j]; d[j] = dst[e + j]; t[j] = et[e + j]; }
        float4 hv[4], rv[4];
#pragma unroll
        for (int j = 0; j < 4; j++) hv[j] = *(const float4*)(h   + (size_t)s[j] * RANK + col);
#pragma unroll
        for (int j = 0; j < 4; j++) rv[j] = *(const float4*)(rel + (size_t)t[j] * RANK + col);
#pragma unroll
        for (int j = 0; j < 4; j++) {
            float4 v;
            v.x = hv[j].x + rv[j].x; v.y = hv[j].y + rv[j].y;
            v.z = hv[j].z + rv[j].z; v.w = hv[j].w + rv[j].w;
            float* p = acc + (size_t)d[j] * RANK + col;
            asm volatile("red.global.add.v4.f32 [%0], {%1, %2, %3, %4};"
                         :: "l"(p), "f"(v.x), "f"(v.y), "f"(v.z), "f"(v.w) : "memory");
        }
    }
}

// Rows with in_deg==0 (expected ~2): out[row] = leaky(h[row] @ Wa)
__global__ void fixup_kernel(const float* __restrict__ B,
                             const float* __restrict__ Wa,
                             const int* __restrict__ zlist,
                             const int* __restrict__ zcount,
                             float* __restrict__ out) {
    int lane  = threadIdx.x & 31;
    int warp  = (blockIdx.x * blockDim.x + threadIdx.x) >> 5;
    int nwarp = (gridDim.x * blockDim.x) >> 5;
    int cnt   = *zcount;
    for (int idx = warp; idx < cnt; idx += nwarp) {
        int row = zlist[idx];
        float a0 = 0.f, a1 = 0.f, a2 = 0.f, a3 = 0.f;
        const float* brow = B + (size_t)row * RANK;
#pragma unroll 4
        for (int k = 0; k < RANK; k++) {
            float hk = __ldg(brow + k);
            float4 w = *(const float4*)(Wa + (size_t)k * RANK + lane * 4);
            a0 = fmaf(hk, w.x, a0); a1 = fmaf(hk, w.y, a1);
            a2 = fmaf(hk, w.z, a2); a3 = fmaf(hk, w.w, a3);
        }
        float4 v;
        v.x = (a0 >= 0.f) ? a0 : a0 * SLOPE;
        v.y = (a1 >= 0.f) ? a1 : a1 * SLOPE;
        v.z = (a2 >= 0.f) ? a2 : a2 * SLOPE;
        v.w = (a3 >= 0.f) ? a3 : a3 * SLOPE;
        *(float4*)(out + (size_t)row * RANK + lane * 4) = v;
    }
}

// ======================= HMMA (mma.sync) GEMM kernel =======================
// out = leaky( (norm*acc) @ Wn + h @ Wl ), 64x128 tile per CTA, bf16 hi/lo
// split (3 MMA terms). W pre-split. 2 CTAs/SM. Half-1 X register-prefetched
// during half-0 MMA so the inter-half fill has no exposed global latency.

__device__ __forceinline__ uint32_t smem_u32(const void* p) {
    uint32_t a;
    asm("{ .reg .u64 t; cvta.to.shared.u64 t, %1; cvt.u32.u64 %0, t; }" : "=r"(a) : "l"(p));
    return a;
}
__device__ __forceinline__ void ldsm_x4(uint32_t& r0, uint32_t& r1, uint32_t& r2, uint32_t& r3,
                                        uint32_t addr) {
    asm volatile("ldmatrix.sync.aligned.m8n8.x4.shared.b16 {%0,%1,%2,%3}, [%4];"
                 : "=r"(r0), "=r"(r1), "=r"(r2), "=r"(r3) : "r"(addr));
}
__device__ __forceinline__ void ldsm_x4_t(uint32_t& r0, uint32_t& r1, uint32_t& r2, uint32_t& r3,
                                          uint32_t addr) {
    asm volatile("ldmatrix.sync.aligned.m8n8.x4.trans.shared.b16 {%0,%1,%2,%3}, [%4];"
                 : "=r"(r0), "=r"(r1), "=r"(r2), "=r"(r3) : "r"(addr));
}
__device__ __forceinline__ void mma16816(float* c, const uint32_t* a, const uint32_t* b) {
    asm volatile(
        "mma.sync.aligned.m16n8k16.row.col.f32.bf16.bf16.f32 "
        "{%0,%1,%2,%3}, {%4,%5,%6,%7}, {%8,%9}, {%0,%1,%2,%3};"
        : "+f"(c[0]), "+f"(c[1]), "+f"(c[2]), "+f"(c[3])
        : "r"(a[0]), "r"(a[1]), "r"(a[2]), "r"(a[3]), "r"(b[0]), "r"(b[1]));
}

#define TSTRIDE 136                     // bf16 elements per smem row (128 + 8 pad)
#define XTILE_B (64 * TSTRIDE * 2)      // 17408 bytes (64-row X tile)
#define WTILE_B (128 * TSTRIDE * 2)     // 34816 bytes (128-row W tile)
#define XHI 0
#define XLO (XTILE_B)
#define WHI (2 * XTILE_B)
#define WLO (2 * XTILE_B + WTILE_B)
#define SM_TOTAL (2 * XTILE_B + 2 * WTILE_B)   // 104448 bytes -> 2 CTAs/SM

// split 8 fp32 -> bf16 hi / bf16 lo, store 16B each into two tiles
__device__ __forceinline__ void split_store8(char* sm, uint32_t hi_base, uint32_t lo_base,
                                             uint32_t byteoff, const float* v) {
    uint32_t hp[4], lp[4];
#pragma unroll
    for (int j = 0; j < 4; j++) {
        __nv_bfloat16 h0 = __float2bfloat16(v[2 * j]);
        __nv_bfloat16 h1 = __float2bfloat16(v[2 * j + 1]);
        float l0 = v[2 * j]     - __bfloat162float(h0);
        float l1 = v[2 * j + 1] - __bfloat162float(h1);
        __nv_bfloat16 g0 = __float2bfloat16(l0);
        __nv_bfloat16 g1 = __float2bfloat16(l1);
        hp[j] = (uint32_t)__bfloat16_as_ushort(h0) | ((uint32_t)__bfloat16_as_ushort(h1) << 16);
        lp[j] = (uint32_t)__bfloat16_as_ushort(g0) | ((uint32_t)__bfloat16_as_ushort(g1) << 16);
    }
    *(uint4*)(sm + hi_base + byteoff) = make_uint4(hp[0], hp[1], hp[2], hp[3]);
    *(uint4*)(sm + lo_base + byteoff) = make_uint4(lp[0], lp[1], lp[2], lp[3]);
}

__global__ __launch_bounds__(256, 2)
void gemm_mma_kernel(const float* __restrict__ A,     // acc [NE,128]
                     const float* __restrict__ B,     // h   [NE,128]
                     const unsigned short* __restrict__ whi,  // layer base: [Wn_hi | Wl_hi]
                     const unsigned short* __restrict__ wlo,
                     const float* __restrict__ norm,
                     float* __restrict__ out) {
    extern __shared__ char sm[];
    uint32_t smb = smem_u32(sm);
    int tid    = threadIdx.x;
    int lane   = tid & 31;
    int wid    = tid >> 5;
    int warp_m = wid & 1;     // 32-row band within the 64-row tile
    int warp_n = wid >> 1;    // 32-col band (4 warps cover N=128)
    int row0   = blockIdx.x * 64;

    // per-thread fill coordinates (4 chunks of 8 elements)
    int frow[4], fk0[4];
    bool fok[4];
#pragma unroll
    for (int cc = 0; cc < 4; cc++) {
        int idx = tid + cc * 256;
        frow[cc] = idx >> 4;
        fk0[cc]  = (idx & 15) << 3;
        fok[cc]  = (row0 + frow[cc]) < NE;
    }

    float c[2][4][4];
#pragma unroll
    for (int mf = 0; mf < 2; mf++)
#pragma unroll
        for (int nf = 0; nf < 4; nf++)
#pragma unroll
            for (int q = 0; q < 4; q++) c[mf][nf][q] = 0.f;

    // ---------- fill half 0: X = norm * acc ----------
    float v[4][8];
#pragma unroll
    for (int cc = 0; cc < 4; cc++) {
        if (fok[cc]) {
            int grow = row0 + frow[cc];
            float4 x0 = *(const float4*)(A + (size_t)grow * RANK + fk0[cc]);
            float4 x1 = *(const float4*)(A + (size_t)grow * RANK + fk0[cc] + 4);
            float s = __ldg(norm + grow);
            v[cc][0] = x0.x * s; v[cc][1] = x0.y * s; v[cc][2] = x0.z * s; v[cc][3] = x0.w * s;
            v[cc][4] = x1.x * s; v[cc][5] = x1.y * s; v[cc][6] = x1.z * s; v[cc][7] = x1.w * s;
        } else {
#pragma unroll
            for (int j = 0; j < 8; j++) v[cc][j] = 0.f;
        }
    }
#pragma unroll
    for (int cc = 0; cc < 4; cc++)
        split_store8(sm, XHI, XLO, (uint32_t)(frow[cc] * TSTRIDE + fk0[cc]) * 2, v[cc]);

    // W half 0 copy
#pragma unroll 1
    for (int i = tid; i < 2048; i += 256) {
        int k  = i >> 4;
        int n0 = (i & 15) << 3;
        uint4 hv = *(const uint4*)(whi + k * RANK + n0);
        uint4 lv = *(const uint4*)(wlo + k * RANK + n0);
        uint32_t off = (uint32_t)(k * TSTRIDE + n0) * 2;
        *(uint4*)(sm + WHI + off) = hv;
        *(uint4*)(sm + WLO + off) = lv;
    }
    __syncthreads();

    // ---------- prefetch half 1 X (h) into registers; consumed after ks loop ----------
#pragma unroll
    for (int cc = 0; cc < 4; cc++) {
        if (fok[cc]) {
            int grow = row0 + frow[cc];
            float4 x0 = *(const float4*)(B + (size_t)grow * RANK + fk0[cc]);
            float4 x1 = *(const float4*)(B + (size_t)grow * RANK + fk0[cc] + 4);
            v[cc][0] = x0.x; v[cc][1] = x0.y; v[cc][2] = x0.z; v[cc][3] = x0.w;
            v[cc][4] = x1.x; v[cc][5] = x1.y; v[cc][6] = x1.z; v[cc][7] = x1.w;
        } else {
#pragma unroll
            for (int j = 0; j < 8; j++) v[cc][j] = 0.f;
        }
    }

    // ---------- MMA half 0 + fill half 1 + MMA half 1 ----------
#pragma unroll 1
    for (int half = 0; half < 2; half++) {
#pragma unroll 1
        for (int ks = 0; ks < 8; ks++) {
            int k0 = ks * 16;
            uint32_t aH[2][4], aL[2][4];
#pragma unroll
            for (int mf = 0; mf < 2; mf++) {
                int row = warp_m * 32 + mf * 16 + (lane & 15);
                int col = k0 + (lane >> 4) * 8;
                uint32_t off = (uint32_t)(row * TSTRIDE + col) * 2;
                ldsm_x4(aH[mf][0], aH[mf][1], aH[mf][2], aH[mf][3], smb + XHI + off);
                ldsm_x4(aL[mf][0], aL[mf][1], aL[mf][2], aL[mf][3], smb + XLO + off);
            }
            uint32_t bH[4][2], bL[4][2];
#pragma unroll
            for (int nb = 0; nb < 2; nb++) {
                int n0   = warp_n * 32 + nb * 16;
                int krow = k0 + ((lane >> 3) & 1) * 8 + (lane & 7);
                int ncol = n0 + (lane >> 4) * 8;
                uint32_t off = (uint32_t)(krow * TSTRIDE + ncol) * 2;
                uint32_t r0, r1, r2, r3;
                ldsm_x4_t(r0, r1, r2, r3, smb + WHI + off);
                bH[nb * 2][0] = r0; bH[nb * 2][1] = r1;
                bH[nb * 2 + 1][0] = r2; bH[nb * 2 + 1][1] = r3;
                ldsm_x4_t(r0, r1, r2, r3, smb + WLO + off);
                bL[nb * 2][0] = r0; bL[nb * 2][1] = r1;
                bL[nb * 2 + 1][0] = r2; bL[nb * 2 + 1][1] = r3;
            }
#pragma unroll
            for (int mf = 0; mf < 2; mf++)
#pragma unroll
                for (int nf = 0; nf < 4; nf++) {
                    mma16816(c[mf][nf], aH[mf], bH[nf]);   // hi*hi
                    mma16816(c[mf][nf], aH[mf], bL[nf]);   // hi*lo
                    mma16816(c[mf][nf], aL[mf], bH[nf]);   // lo*hi
                }
        }

        if (half == 0) {
            __syncthreads();   // done reading half-0 tiles
            // store prefetched X (h) — loads completed during the MMA loop
#pragma unroll
            for (int cc = 0; cc < 4; cc++)
                split_store8(sm, XHI, XLO, (uint32_t)(frow[cc] * TSTRIDE + fk0[cc]) * 2, v[cc]);
            // W half 1 copy (L2-hot)
            const unsigned short* WH = whi + RANK * RANK;
            const unsigned short* WL = wlo + RANK * RANK;
#pragma unroll 1
            for (int i = tid; i < 2048; i += 256) {
                int k  = i >> 4;
                int n0 = (i & 15) << 3;
                uint4 hv = *(const uint4*)(WH + k * RANK + n0);
                uint4 lv = *(const uint4*)(WL + k * RANK + n0);
                uint32_t off = (uint32_t)(k * TSTRIDE + n0) * 2;
                *(uint4*)(sm + WHI + off) = hv;
                *(uint4*)(sm + WLO + off) = lv;
            }
            __syncthreads();
        }
    }

    // ---------- epilogue: leaky relu + store ----------
    int r_in  = lane >> 2;
    int c_in  = (lane & 3) * 2;
#pragma unroll
    for (int mf = 0; mf < 2; mf++) {
        int rbase = row0 + warp_m * 32 + mf * 16 + r_in;
#pragma unroll
        for (int nf = 0; nf < 4; nf++) {
            int col = warp_n * 32 + nf * 8 + c_in;
            float x0 = c[mf][nf][0], x1 = c[mf][nf][1];
            float x2 = c[mf][nf][2], x3 = c[mf][nf][3];
            x0 = (x0 >= 0.f) ? x0 : x0 * SLOPE;
            x1 = (x1 >= 0.f) ? x1 : x1 * SLOPE;
            x2 = (x2 >= 0.f) ? x2 : x2 * SLOPE;
            x3 = (x3 >= 0.f) ? x3 : x3 * SLOPE;
            if (rbase < NE)
                *(float2*)(out + (size_t)rbase * RANK + col) = make_float2(x0, x1);
            if (rbase + 8 < NE)
                *(float2*)(out + (size_t)(rbase + 8) * RANK + col) = make_float2(x2, x3);
        }
    }
}

// ======================= launch =======================
extern "C" void kernel_launch(void* const* d_in, const int* in_sizes, int n_in,
                              void* d_out, int out_size) {
    const float* ent  = (const float*)d_in[0];
    const float* rel  = (const float*)d_in[1];
    const float* norm = (const float*)d_in[2];
    const float* Wn   = (const float*)d_in[3];
    const float* Wl   = (const float*)d_in[4];
    const float* Wa   = (const float*)d_in[5];
    const int*   src  = (const int*)d_in[6];
    const int*   dst  = (const int*)d_in[7];
    const int*   et   = (const int*)d_in[8];
    float* out = (float*)d_out;

    void *p_h2, *p_acc, *p_hasin, *p_zlist, *p_zcount, *p_whi, *p_wlo;
    cudaGetSymbolAddress(&p_h2, g_h2);
    cudaGetSymbolAddress(&p_acc, g_acc);
    cudaGetSymbolAddress(&p_hasin, g_hasin);
    cudaGetSymbolAddress(&p_zlist, g_zlist);
    cudaGetSymbolAddress(&p_zcount, g_zcount);
    cudaGetSymbolAddress(&p_whi, g_whi);
    cudaGetSymbolAddress(&p_wlo, g_wlo);
    float* h2    = (float*)p_h2;
    float* acc   = (float*)p_acc;
    int* hasin   = (int*)p_hasin;
    int* zlist   = (int*)p_zlist;
    int* zcount  = (int*)p_zcount;
    unsigned short* whi = (unsigned short*)p_whi;
    unsigned short* wlo = (unsigned short*)p_wlo;

    const int WOFF = RANK * RANK;  // per-layer weight offset

    cudaFuncSetAttribute(gemm_mma_kernel, cudaFuncAttributeMaxDynamicSharedMemorySize, SM_TOTAL);

    cudaMemsetAsync(hasin, 0, NE * sizeof(int), 0);
    cudaMemsetAsync(zcount, 0, sizeof(int), 0);
    mark_hasin_kernel<<<(EDGES + 255) / 256, 256>>>(dst, hasin);
    build_zlist_kernel<<<(NE + 255) / 256, 256>>>(hasin, zlist, zcount);
    wsplit_kernel<<<(4 * RANK * RANK + 255) / 256, 256>>>(Wn, Wl, whi, wlo);

    const int tiles = (NE + 63) / 64;

    // ---- layer 0: h = ent_emb ----
    cudaMemsetAsync(acc, 0, (size_t)NE * RANK * sizeof(float), 0);
    scatter_kernel<<<2048, 256>>>(ent, rel, src, dst, et, acc);
    gemm_mma_kernel<<<tiles, 256, SM_TOTAL>>>(acc, ent, whi, wlo, norm, h2);
    fixup_kernel<<<32, 256>>>(ent, Wa, zlist, zcount, h2);

    // ---- layer 1: h = h2, write final output ----
    cudaMemsetAsync(acc, 0, (size_t)NE * RANK * sizeof(float), 0);
    scatter_kernel<<<2048, 256>>>(h2, rel, src, dst, et, acc);
    gemm_mma_kernel<<<tiles, 256, SM_TOTAL>>>(acc, h2, whi + 2 * WOFF, wlo + 2 * WOFF, norm, out);
    fixup_kernel<<<32, 256>>>(h2, Wa + WOFF, zlist, zcount, out);
}